// round 1
// baseline (speedup 1.0000x reference)
#include <cuda_runtime.h>
#include <cstdint>

// S5 SSM scan:  x_t = Atilde*x_{t-1} + Btilde*u_t ;  y_t = sum_n C*x
// batch=32, L=4096, D=256, N=64, fp32.
// Mapping: 2 threads per (b,d) channel, each owning 32 states (16 packed f32x2
// pairs) entirely in registers. Warp lanes (2i, 2i+1) pair via shfl.xor(1) to
// reduce y. Block = 128 threads = 64 d-channels for one batch b. Grid = 32 b x
// 4 d-groups = 128 blocks. u staged through double-buffered smem tiles of 64
// timesteps via cp.async.

#define SEQ    4096
#define DMODEL 256
#define DSTATE 64
#define TT     64      // timesteps per smem tile
#define DG     64      // d-channels per block
#define NTHREADS 128   // DG * 2
#define JH     16      // packed f32x2 pairs per thread (32 states)

typedef unsigned long long u64;

__device__ __forceinline__ u64 pack2(float lo, float hi) {
    u64 r; asm("mov.b64 %0, {%1,%2};" : "=l"(r) : "f"(lo), "f"(hi)); return r;
}
__device__ __forceinline__ float2 unpack2(u64 v) {
    float2 f; asm("mov.b64 {%0,%1}, %2;" : "=f"(f.x), "=f"(f.y) : "l"(v)); return f;
}
__device__ __forceinline__ u64 fma2(u64 a, u64 b, u64 c) {
    u64 d; asm("fma.rn.f32x2 %0, %1, %2, %3;" : "=l"(d) : "l"(a), "l"(b), "l"(c)); return d;
}
__device__ __forceinline__ u64 mul2(u64 a, u64 b) {
    u64 d; asm("mul.rn.f32x2 %0, %1, %2;" : "=l"(d) : "l"(a), "l"(b)); return d;
}
__device__ __forceinline__ u64 add2(u64 a, u64 b) {
    u64 d; asm("add.rn.f32x2 %0, %1, %2;" : "=l"(d) : "l"(a), "l"(b)); return d;
}

__global__ __launch_bounds__(NTHREADS, 1)
void s5_scan_kernel(const float* __restrict__ u,
                    const float* __restrict__ log_dt,
                    const float* __restrict__ A_real,
                    const float* __restrict__ Bm,
                    const float* __restrict__ Cm,
                    const float* __restrict__ x0,
                    float* __restrict__ out)
{
    __shared__ float us[2][TT][DG];   // 2 x 16KB

    const int tid = threadIdx.x;
    const int c   = tid >> 1;     // channel within block (0..63)
    const int h   = tid & 1;      // state half (0: n in [0,32), 1: n in [32,64))
    const int g   = blockIdx.x & 3;        // d-group
    const int b   = blockIdx.x >> 2;       // batch
    const int d   = g * DG + c;

    // ---- init: discretize per-(d, n) coefficients into registers ----
    u64 A2[JH], B2[JH], C2[JH], X2[JH];
    {
        const float dt = expf(log_dt[d]);   // DT_SCALE = 1.0
        const int base = d * DSTATE + h * 32;
        #pragma unroll
        for (int j = 0; j < JH; j++) {
            const float ar0 = A_real[base + 2*j];
            const float ar1 = A_real[base + 2*j + 1];
            const float at0 = expf(ar0 * dt);
            const float at1 = expf(ar1 * dt);
            const float bt0 = (1.0f - at0) * Bm[base + 2*j]     / ar0;
            const float bt1 = (1.0f - at1) * Bm[base + 2*j + 1] / ar1;
            A2[j] = pack2(at0, at1);
            B2[j] = pack2(bt0, bt1);
            C2[j] = pack2(Cm[base + 2*j], Cm[base + 2*j + 1]);
            X2[j] = pack2(x0[base + 2*j], x0[base + 2*j + 1]);
        }
    }

    // ---- tile prefetch helper (cp.async, 16B granules) ----
    const uint32_t sb0 = (uint32_t)__cvta_generic_to_shared(&us[0][0][0]);
    const uint32_t sb1 = (uint32_t)__cvta_generic_to_shared(&us[1][0][0]);
    const float* gbase = u + ((size_t)b * SEQ) * DMODEL + g * DG;

    auto load_tile = [&](int t0, int s) {
        const uint32_t sbase = s ? sb1 : sb0;
        #pragma unroll
        for (int k = 0; k < 8; k++) {
            const int idx = tid + k * NTHREADS;      // 0..1023 float4 slots
            const int row = idx >> 4;                // timestep within tile
            const int col = idx & 15;                // float4 within row
            const float* gp = gbase + (size_t)(t0 + row) * DMODEL + col * 4;
            const uint32_t sa = sbase + (uint32_t)((row * DG + col * 4) * 4);
            asm volatile("cp.async.cg.shared.global [%0], [%1], 16;" :: "r"(sa), "l"(gp));
        }
        asm volatile("cp.async.commit_group;" ::: "memory");
    };

    const int NT = SEQ / TT;   // 64 tiles
    load_tile(0, 0);

    for (int tile = 0; tile < NT; ++tile) {
        const int cur = tile & 1;
        asm volatile("cp.async.wait_group 0;" ::: "memory");
        __syncthreads();
        if (tile + 1 < NT) load_tile((tile + 1) * TT, cur ^ 1);

        const float* up = &us[cur][0][c];
        float* op = out + ((size_t)b * SEQ + (size_t)tile * TT) * DMODEL + d;

        #pragma unroll 2
        for (int tt = 0; tt < TT; ++tt) {
            const float uv = up[tt * DG];          // broadcast within lane pair
            const u64 ub = pack2(uv, uv);

            u64 t, ya, yb, yc, yd;
            t = mul2(B2[0], ub); X2[0] = fma2(A2[0], X2[0], t); ya = mul2(C2[0], X2[0]);
            t = mul2(B2[1], ub); X2[1] = fma2(A2[1], X2[1], t); yb = mul2(C2[1], X2[1]);
            t = mul2(B2[2], ub); X2[2] = fma2(A2[2], X2[2], t); yc = mul2(C2[2], X2[2]);
            t = mul2(B2[3], ub); X2[3] = fma2(A2[3], X2[3], t); yd = mul2(C2[3], X2[3]);
            #pragma unroll
            for (int j = 4; j < JH; j += 4) {
                t = mul2(B2[j+0], ub); X2[j+0] = fma2(A2[j+0], X2[j+0], t); ya = fma2(C2[j+0], X2[j+0], ya);
                t = mul2(B2[j+1], ub); X2[j+1] = fma2(A2[j+1], X2[j+1], t); yb = fma2(C2[j+1], X2[j+1], yb);
                t = mul2(B2[j+2], ub); X2[j+2] = fma2(A2[j+2], X2[j+2], t); yc = fma2(C2[j+2], X2[j+2], yc);
                t = mul2(B2[j+3], ub); X2[j+3] = fma2(A2[j+3], X2[j+3], t); yd = fma2(C2[j+3], X2[j+3], yd);
            }

            const u64 ysum2 = add2(add2(ya, yb), add2(yc, yd));
            const float2 f = unpack2(ysum2);
            const float ys = f.x + f.y;                       // this half's partial
            const float tot = ys + __shfl_xor_sync(0xffffffffu, ys, 1);
            if (h == 0) op[(size_t)tt * DMODEL] = tot;
        }
    }
}

extern "C" void kernel_launch(void* const* d_in, const int* in_sizes, int n_in,
                              void* d_out, int out_size)
{
    const float* u      = (const float*)d_in[0];
    const float* log_dt = (const float*)d_in[1];
    const float* A_real = (const float*)d_in[2];
    const float* B      = (const float*)d_in[3];
    const float* C      = (const float*)d_in[4];
    const float* x0     = (const float*)d_in[5];
    float* out = (float*)d_out;

    s5_scan_kernel<<<128, NTHREADS>>>(u, log_dt, A_real, B, C, x0, out);
}

// round 2
// speedup vs baseline: 1.5956x; 1.5956x over previous
#include <cuda_runtime.h>
#include <cstdint>

// S5 SSM scan, B-folded form:
//   x'_t = Atilde * x'_{t-1} + u_t          (input is the FMA addend, no mul!)
//   y_t  = sum_n (C*Btilde)_n * x'_{t,n}
// where x' = x / Btilde  (valid since y only sees C*Btilde*x').
// batch=32, L=4096, D=256, N=64, fp32.
//
// Mapping: 4 threads per (b,d) channel, each owning 16 states (8 packed f32x2
// pairs) in registers. Lanes (4i..4i+3) reduce y via 2 shfl.xor. Block = 256
// threads = 64 d-channels for one batch. Grid = 32 b x 4 d-groups = 128 blocks,
// 8 warps/SM (2 per SMSP). u double-buffered in smem via cp.async.

#define SEQ    4096
#define DMODEL 256
#define DSTATE 64
#define TT     64      // timesteps per smem tile
#define DG     64      // d-channels per block
#define NTHREADS 256   // DG * 4
#define JH     8       // packed f32x2 pairs per thread (16 states)

typedef unsigned long long u64;

__device__ __forceinline__ u64 pack2(float lo, float hi) {
    u64 r; asm("mov.b64 %0, {%1,%2};" : "=l"(r) : "f"(lo), "f"(hi)); return r;
}
__device__ __forceinline__ float2 unpack2(u64 v) {
    float2 f; asm("mov.b64 {%0,%1}, %2;" : "=f"(f.x), "=f"(f.y) : "l"(v)); return f;
}
__device__ __forceinline__ u64 fma2(u64 a, u64 b, u64 c) {
    u64 d; asm("fma.rn.f32x2 %0, %1, %2, %3;" : "=l"(d) : "l"(a), "l"(b), "l"(c)); return d;
}
__device__ __forceinline__ u64 mul2(u64 a, u64 b) {
    u64 d; asm("mul.rn.f32x2 %0, %1, %2;" : "=l"(d) : "l"(a), "l"(b)); return d;
}
__device__ __forceinline__ u64 add2(u64 a, u64 b) {
    u64 d; asm("add.rn.f32x2 %0, %1, %2;" : "=l"(d) : "l"(a), "l"(b)); return d;
}

__global__ __launch_bounds__(NTHREADS, 1)
void s5_scan_kernel(const float* __restrict__ u,
                    const float* __restrict__ log_dt,
                    const float* __restrict__ A_real,
                    const float* __restrict__ Bm,
                    const float* __restrict__ Cm,
                    const float* __restrict__ x0,
                    float* __restrict__ out)
{
    __shared__ float us[2][TT][DG];   // 2 x 16KB

    const int tid = threadIdx.x;
    const int c   = tid >> 2;     // channel within block (0..63)
    const int h   = tid & 3;      // state quarter (16 states each)
    const int g   = blockIdx.x & 3;        // d-group
    const int b   = blockIdx.x >> 2;       // batch
    const int d   = g * DG + c;

    // ---- init: discretize + fold Btilde into C ----
    u64 A2[JH], C2[JH], X2[JH];
    {
        const float dt = expf(log_dt[d]);   // DT_SCALE = 1.0
        const int base = d * DSTATE + h * 16;
        #pragma unroll
        for (int j = 0; j < JH; j++) {
            const float ar0 = A_real[base + 2*j];
            const float ar1 = A_real[base + 2*j + 1];
            const float at0 = expf(ar0 * dt);
            const float at1 = expf(ar1 * dt);
            const float bt0 = (1.0f - at0) * Bm[base + 2*j]     / ar0;
            const float bt1 = (1.0f - at1) * Bm[base + 2*j + 1] / ar1;
            A2[j] = pack2(at0, at1);
            C2[j] = pack2(Cm[base + 2*j] * bt0, Cm[base + 2*j + 1] * bt1);
            const float xv0 = x0[base + 2*j];
            const float xv1 = x0[base + 2*j + 1];
            const float xp0 = (bt0 != 0.0f) ? (xv0 / bt0) : 0.0f;
            const float xp1 = (bt1 != 0.0f) ? (xv1 / bt1) : 0.0f;
            X2[j] = pack2(xp0, xp1);
        }
    }

    // ---- tile prefetch (cp.async, 16B granules) ----
    const uint32_t sb0 = (uint32_t)__cvta_generic_to_shared(&us[0][0][0]);
    const uint32_t sb1 = (uint32_t)__cvta_generic_to_shared(&us[1][0][0]);
    const float* gbase = u + ((size_t)b * SEQ) * DMODEL + g * DG;

    auto load_tile = [&](int t0, int s) {
        const uint32_t sbase = s ? sb1 : sb0;
        #pragma unroll
        for (int k = 0; k < 4; k++) {
            const int idx = tid + k * NTHREADS;      // 0..1023 float4 slots
            const int row = idx >> 4;                // timestep within tile
            const int col = idx & 15;                // float4 within row
            const float* gp = gbase + (size_t)(t0 + row) * DMODEL + col * 4;
            const uint32_t sa = sbase + (uint32_t)((row * DG + col * 4) * 4);
            asm volatile("cp.async.cg.shared.global [%0], [%1], 16;" :: "r"(sa), "l"(gp));
        }
        asm volatile("cp.async.commit_group;" ::: "memory");
    };

    const int NT = SEQ / TT;   // 64 tiles
    load_tile(0, 0);

    for (int tile = 0; tile < NT; ++tile) {
        const int cur = tile & 1;
        asm volatile("cp.async.wait_group 0;" ::: "memory");
        __syncthreads();
        if (tile + 1 < NT) load_tile((tile + 1) * TT, cur ^ 1);

        const float* up = &us[cur][0][c];
        float* op = out + ((size_t)b * SEQ + (size_t)tile * TT) * DMODEL + d;

        #pragma unroll 1
        for (int tt = 0; tt < TT; tt += 4) {
            // prefetch 4 timesteps of u into registers up front
            const float uv0 = up[(tt + 0) * DG];
            const float uv1 = up[(tt + 1) * DG];
            const float uv2 = up[(tt + 2) * DG];
            const float uv3 = up[(tt + 3) * DG];
            const u64 ubv[4] = { pack2(uv0, uv0), pack2(uv1, uv1),
                                 pack2(uv2, uv2), pack2(uv3, uv3) };

            #pragma unroll
            for (int i = 0; i < 4; ++i) {
                const u64 ub = ubv[i];
                u64 ya, yb;
                X2[0] = fma2(A2[0], X2[0], ub);  ya = mul2(C2[0], X2[0]);
                X2[1] = fma2(A2[1], X2[1], ub);  yb = mul2(C2[1], X2[1]);
                #pragma unroll
                for (int j = 2; j < JH; j += 2) {
                    X2[j]   = fma2(A2[j],   X2[j],   ub);  ya = fma2(C2[j],   X2[j],   ya);
                    X2[j+1] = fma2(A2[j+1], X2[j+1], ub);  yb = fma2(C2[j+1], X2[j+1], yb);
                }
                const float2 f = unpack2(add2(ya, yb));
                float ys = f.x + f.y;                         // this quarter's partial
                ys += __shfl_xor_sync(0xffffffffu, ys, 1);
                ys += __shfl_xor_sync(0xffffffffu, ys, 2);
                if (h == 0) op[(size_t)(tt + i) * DMODEL] = ys;
            }
        }
    }
}

extern "C" void kernel_launch(void* const* d_in, const int* in_sizes, int n_in,
                              void* d_out, int out_size)
{
    const float* u      = (const float*)d_in[0];
    const float* log_dt = (const float*)d_in[1];
    const float* A_real = (const float*)d_in[2];
    const float* B      = (const float*)d_in[3];
    const float* C      = (const float*)d_in[4];
    const float* x0     = (const float*)d_in[5];
    float* out = (float*)d_out;

    s5_scan_kernel<<<128, NTHREADS>>>(u, log_dt, A_real, B, C, x0, out);
}